// round 4
// baseline (speedup 1.0000x reference)
#include <cuda_runtime.h>

// Problem constants (from reference): N=32, RES=256, C=2, K=1024, T=1, EPS=1e-6
#define NB   32
#define RESO 256
#define KP   1024
#define EPSF 1e-6f

// Scratch (no allocations allowed) --------------------------------------------
__device__ float g_srcp[NB * KP * 2];   // sampled src features + EPS
__device__ float g_trgc[NB * KP * 2];   // sampled trg features
__device__ float g_loss[NB * KP];       // per-(n,j) unweighted loss (2*ce)

// MUFU intrinsics -------------------------------------------------------------
__device__ __forceinline__ float ex2a(float x)  { float y; asm("ex2.approx.f32 %0, %1;"   : "=f"(y) : "f"(x)); return y; }
__device__ __forceinline__ float lg2a(float x)  { float y; asm("lg2.approx.f32 %0, %1;"   : "=f"(y) : "f"(x)); return y; }
__device__ __forceinline__ float rsqa(float x)  { float y; asm("rsqrt.approx.f32 %0, %1;" : "=f"(y) : "f"(x)); return y; }

__device__ __forceinline__ float psqrt(float sq) {        // sqrt via rsqrt, NaN-guarded
    return sq * rsqa(fmaxf(sq, 1e-30f));
}

// Bilinear sample with zero-padding + align_corners=True (pixel coords) -------
__device__ __forceinline__ float2 bsample(const float* __restrict__ flow, int n, float x, float y) {
    float x0f = floorf(x), y0f = floorf(y);
    int   x0  = (int)x0f,  y0  = (int)y0f;
    float wx  = x - x0f,   wy  = y - y0f;
    float ax = 0.f, ay = 0.f;
#pragma unroll
    for (int dy = 0; dy < 2; dy++) {
#pragma unroll
        for (int dx = 0; dx < 2; dx++) {
            int xi = x0 + dx, yi = y0 + dy;
            if (xi >= 0 && xi < RESO && yi >= 0 && yi < RESO) {
                float w = (dx ? wx : 1.f - wx) * (dy ? wy : 1.f - wy);
                const float2 v = *(const float2*)(flow + ((((size_t)n * RESO + yi) * RESO + xi) << 1));
                ax = fmaf(v.x, w, ax);
                ay = fmaf(v.y, w, ay);
            }
        }
    }
    return make_float2(ax, ay);
}

// Kernel 1: sample both feature sets ------------------------------------------
__global__ void sample_kernel(const float* __restrict__ sflow, const float* __restrict__ tflow,
                              const float* __restrict__ skp,  const float* __restrict__ tkp) {
    int idx = blockIdx.x * blockDim.x + threadIdx.x;       // n*K + k
    if (idx >= NB * KP) return;
    int n = idx >> 10;
    float2 s = bsample(sflow, n, skp[2 * idx], skp[2 * idx + 1]);
    g_srcp[2 * idx]     = s.x + EPSF;                      // fold +eps into src side
    g_srcp[2 * idx + 1] = s.y + EPSF;
    float2 t = bsample(tflow, n, tkp[2 * idx], tkp[2 * idx + 1]);
    g_trgc[2 * idx]     = t.x;
    g_trgc[2 * idx + 1] = t.y;
}

// Kernel 2: pairwise distances + CE diag. 1 warp per (n, j). ------------------
// Block = 256 threads = 8 warps = 8 j's. Grid = NB * (KP/8) = 4096 blocks.
__global__ __launch_bounds__(256) void pair_kernel() {
    __shared__ float2 sh[KP];                              // src features of batch n (8 KB)
    const int warp = threadIdx.x >> 5, lane = threadIdx.x & 31;
    const int n     = blockIdx.x >> 7;                     // 128 blocks per batch
    const int jbase = (blockIdx.x & 127) << 3;

    const float2* __restrict__ srcp = (const float2*)g_srcp + n * KP;
    for (int i = threadIdx.x; i < KP; i += 256) sh[i] = srcp[i];
    __syncthreads();

    const int j = jbase + warp;
    const float2 t = ((const float2*)g_trgc)[n * KP + j];

    // Diagonal distance computed once (hoisted out of the hot loop)
    float2 sj = sh[j];
    float ddx = sj.x - t.x, ddy = sj.y - t.y;
    const float diag = psqrt(fmaf(ddx, ddx, ddy * ddy));

    const float C1 = -1.4426950408889634f;                 // -log2(e) / T
    float acc = 0.f;
#pragma unroll 8
    for (int i = lane; i < KP; i += 32) {
        float2 s  = sh[i];
        float dx  = s.x - t.x;
        float dy  = s.y - t.y;
        float dist = psqrt(fmaf(dx, dx, dy * dy));
        acc += ex2a(dist * C1);                            // exp(-dist)
    }
#pragma unroll
    for (int o = 16; o; o >>= 1)
        acc += __shfl_xor_sync(0xffffffffu, acc, o);
    if (lane == 0)
        // ce = LSE - logit_jj = ln(acc) + dist_jj ; d1==d2 forward => factor 2
        g_loss[n * KP + j] = 2.f * fmaf(lg2a(acc), 0.6931471805599453f, diag);
}

// Kernel 3: deterministic weighted reduction ----------------------------------
__global__ __launch_bounds__(1024) void reduce_kernel(const int* __restrict__ vis,
                                                      const float* __restrict__ wt,
                                                      float* __restrict__ out) {
    __shared__ float sh_l[32], sh_v[32];
    float l = 0.f, v = 0.f;
    for (int i = threadIdx.x; i < NB * KP; i += 1024) {
        float vi = vis[i] ? 1.f : 0.f;
        l = fmaf(g_loss[i] * wt[i], vi, l);
        v += vi;
    }
    int lane = threadIdx.x & 31, w = threadIdx.x >> 5;
#pragma unroll
    for (int o = 16; o; o >>= 1) {
        l += __shfl_xor_sync(0xffffffffu, l, o);
        v += __shfl_xor_sync(0xffffffffu, v, o);
    }
    if (lane == 0) { sh_l[w] = l; sh_v[w] = v; }
    __syncthreads();
    if (w == 0) {
        l = sh_l[lane]; v = sh_v[lane];
#pragma unroll
        for (int o = 16; o; o >>= 1) {
            l += __shfl_xor_sync(0xffffffffu, l, o);
            v += __shfl_xor_sync(0xffffffffu, v, o);
        }
        if (lane == 0) out[0] = l / v;
    }
}

extern "C" void kernel_launch(void* const* d_in, const int* in_sizes, int n_in,
                              void* d_out, int out_size) {
    const float* sflow = (const float*)d_in[0];
    const float* tflow = (const float*)d_in[1];
    const float* skp   = (const float*)d_in[2];
    const float* tkp   = (const float*)d_in[3];
    const int*   vis   = (const int*)d_in[4];   // bool serialized as int32
    const float* wt    = (const float*)d_in[5];
    float*       out   = (float*)d_out;

    sample_kernel<<<(NB * KP + 255) / 256, 256>>>(sflow, tflow, skp, tkp);
    pair_kernel<<<NB * (KP / 8), 256>>>();
    reduce_kernel<<<1, 1024>>>(vis, wt, out);
}

// round 5
// speedup vs baseline: 1.1331x; 1.1331x over previous
#include <cuda_runtime.h>

// Problem constants (from reference): N=32, RES=256, C=2, K=1024, T=1, EPS=1e-6
#define NB   32
#define RESO 256
#define KP   1024
#define EPSF 1e-6f

// Scratch (no allocations allowed) --------------------------------------------
__device__ float g_srcp[NB * KP * 2];   // sampled src features + EPS
__device__ float g_trgc[NB * KP * 2];   // sampled trg features
__device__ float g_part[1024];          // per-block weighted loss partials
__device__ float g_cnt [1024];          // per-block visibility counts

// MUFU intrinsics -------------------------------------------------------------
__device__ __forceinline__ float ex2a(float x)  { float y; asm("ex2.approx.f32 %0, %1;"   : "=f"(y) : "f"(x)); return y; }
__device__ __forceinline__ float lg2a(float x)  { float y; asm("lg2.approx.f32 %0, %1;"   : "=f"(y) : "f"(x)); return y; }
__device__ __forceinline__ float rsqa(float x)  { float y; asm("rsqrt.approx.f32 %0, %1;" : "=f"(y) : "f"(x)); return y; }

__device__ __forceinline__ float psqrt(float sq) {        // sqrt via rsqrt, NaN-guarded
    return sq * rsqa(fmaxf(sq, 1e-30f));
}

// Bilinear sample with zero-padding + align_corners=True (pixel coords) -------
__device__ __forceinline__ float2 bsample(const float* __restrict__ flow, int n, float x, float y) {
    float x0f = floorf(x), y0f = floorf(y);
    int   x0  = (int)x0f,  y0  = (int)y0f;
    float wx  = x - x0f,   wy  = y - y0f;
    float ax = 0.f, ay = 0.f;
#pragma unroll
    for (int dy = 0; dy < 2; dy++) {
#pragma unroll
        for (int dx = 0; dx < 2; dx++) {
            int xi = x0 + dx, yi = y0 + dy;
            if (xi >= 0 && xi < RESO && yi >= 0 && yi < RESO) {
                float w = (dx ? wx : 1.f - wx) * (dy ? wy : 1.f - wy);
                const float2 v = *(const float2*)(flow + ((((size_t)n * RESO + yi) * RESO + xi) << 1));
                ax = fmaf(v.x, w, ax);
                ay = fmaf(v.y, w, ay);
            }
        }
    }
    return make_float2(ax, ay);
}

// Kernel 1: one sample per thread (64K threads) -------------------------------
__global__ __launch_bounds__(256) void sample_kernel(
        const float* __restrict__ sflow, const float* __restrict__ tflow,
        const float* __restrict__ skp,  const float* __restrict__ tkp) {
    int idx = blockIdx.x * blockDim.x + threadIdx.x;       // [0, 2*N*K)
    int k   = idx & (NB * KP - 1);                         // n*K + kp index
    int n   = k >> 10;
    if (idx < NB * KP) {
        float2 p = ((const float2*)skp)[k];
        float2 s = bsample(sflow, n, p.x, p.y);
        g_srcp[2 * k]     = s.x + EPSF;                    // fold +eps into src side
        g_srcp[2 * k + 1] = s.y + EPSF;
    } else {
        float2 p = ((const float2*)tkp)[k];
        float2 t = bsample(tflow, n, p.x, p.y);
        g_trgc[2 * k]     = t.x;
        g_trgc[2 * k + 1] = t.y;
    }
}

// Kernel 2: pairwise + CE diag + per-block weighted partial -------------------
// 1 warp = 4 consecutive j's. Block = 8 warps = 32 j's. Grid = 32*32 = 1024.
__global__ __launch_bounds__(256) void pair_kernel(const int* __restrict__ vis,
                                                   const float* __restrict__ wt) {
    __shared__ float2 sh[KP];                              // src features of batch n (8 KB)
    __shared__ float  sh_l[8], sh_v[8];
    const int warp = threadIdx.x >> 5, lane = threadIdx.x & 31;
    const int n     = blockIdx.x >> 5;                     // 32 blocks per batch
    const int jbase = ((blockIdx.x & 31) << 5) + (warp << 2);

    const float2* __restrict__ srcp = (const float2*)g_srcp + n * KP;
    for (int i = threadIdx.x; i < KP; i += 256) sh[i] = srcp[i];
    __syncthreads();

    const float2* __restrict__ trgn = (const float2*)g_trgc + n * KP;
    const float2 t0 = trgn[jbase + 0];
    const float2 t1 = trgn[jbase + 1];
    const float2 t2 = trgn[jbase + 2];
    const float2 t3 = trgn[jbase + 3];

    const float C1 = -1.4426950408889634f;                 // -log2(e) / T
    float a0 = 0.f, a1 = 0.f, a2 = 0.f, a3 = 0.f;
#pragma unroll 4
    for (int i = lane; i < KP; i += 32) {
        float2 s = sh[i];
        { float dx = s.x - t0.x, dy = s.y - t0.y; a0 += ex2a(psqrt(fmaf(dx, dx, dy * dy)) * C1); }
        { float dx = s.x - t1.x, dy = s.y - t1.y; a1 += ex2a(psqrt(fmaf(dx, dx, dy * dy)) * C1); }
        { float dx = s.x - t2.x, dy = s.y - t2.y; a2 += ex2a(psqrt(fmaf(dx, dx, dy * dy)) * C1); }
        { float dx = s.x - t3.x, dy = s.y - t3.y; a3 += ex2a(psqrt(fmaf(dx, dx, dy * dy)) * C1); }
    }
#pragma unroll
    for (int o = 16; o; o >>= 1) {
        a0 += __shfl_xor_sync(0xffffffffu, a0, o);
        a1 += __shfl_xor_sync(0xffffffffu, a1, o);
        a2 += __shfl_xor_sync(0xffffffffu, a2, o);
        a3 += __shfl_xor_sync(0xffffffffu, a3, o);
    }

    if (lane == 0) {
        const float LN2 = 0.6931471805599453f;
        float lsum = 0.f, vsum = 0.f;
        float acc[4] = {a0, a1, a2, a3};
#pragma unroll
        for (int q = 0; q < 4; q++) {
            int j = jbase + q;
            float2 sj = sh[j];
            float dx = sj.x - (q == 0 ? t0.x : q == 1 ? t1.x : q == 2 ? t2.x : t3.x);
            float dy = sj.y - (q == 0 ? t0.y : q == 1 ? t1.y : q == 2 ? t2.y : t3.y);
            float diag = psqrt(fmaf(dx, dx, dy * dy));
            // ce = ln(sum exp) + dist_jj ; d1==d2 forward => factor 2
            float loss = 2.f * fmaf(lg2a(acc[q]), LN2, diag);
            float vi = vis[n * KP + j] ? 1.f : 0.f;
            lsum = fmaf(loss * wt[n * KP + j], vi, lsum);
            vsum += vi;
        }
        sh_l[warp] = lsum; sh_v[warp] = vsum;
    }
    __syncthreads();
    if (threadIdx.x == 0) {
        float l = 0.f, v = 0.f;
#pragma unroll
        for (int w = 0; w < 8; w++) { l += sh_l[w]; v += sh_v[w]; }
        g_part[blockIdx.x] = l;
        g_cnt [blockIdx.x] = v;
    }
}

// Kernel 3: final reduction of 1024 partials ----------------------------------
__global__ __launch_bounds__(1024) void reduce_kernel(float* __restrict__ out) {
    __shared__ float sh_l[32], sh_v[32];
    float l = g_part[threadIdx.x];
    float v = g_cnt [threadIdx.x];
    int lane = threadIdx.x & 31, w = threadIdx.x >> 5;
#pragma unroll
    for (int o = 16; o; o >>= 1) {
        l += __shfl_xor_sync(0xffffffffu, l, o);
        v += __shfl_xor_sync(0xffffffffu, v, o);
    }
    if (lane == 0) { sh_l[w] = l; sh_v[w] = v; }
    __syncthreads();
    if (w == 0) {
        l = sh_l[lane]; v = sh_v[lane];
#pragma unroll
        for (int o = 16; o; o >>= 1) {
            l += __shfl_xor_sync(0xffffffffu, l, o);
            v += __shfl_xor_sync(0xffffffffu, v, o);
        }
        if (lane == 0) out[0] = l / v;
    }
}

extern "C" void kernel_launch(void* const* d_in, const int* in_sizes, int n_in,
                              void* d_out, int out_size) {
    const float* sflow = (const float*)d_in[0];
    const float* tflow = (const float*)d_in[1];
    const float* skp   = (const float*)d_in[2];
    const float* tkp   = (const float*)d_in[3];
    const int*   vis   = (const int*)d_in[4];   // bool serialized as int32
    const float* wt    = (const float*)d_in[5];
    float*       out   = (float*)d_out;

    sample_kernel<<<(2 * NB * KP) / 256, 256>>>(sflow, tflow, skp, tkp);
    pair_kernel<<<1024, 256>>>(vis, wt);
    reduce_kernel<<<1, 1024>>>(out);
}

// round 6
// speedup vs baseline: 1.3355x; 1.1786x over previous
#include <cuda_runtime.h>

// Problem constants (from reference): N=32, RES=256, C=2, K=1024, T=1, EPS=1e-6
#define NB   32
#define RESO 256
#define KP   1024
#define EPSF 1e-6f

// Scratch (no allocations allowed) --------------------------------------------
__device__ float g_srcp[NB * KP * 2];   // sampled src features + EPS
__device__ float g_trgc[NB * KP * 2];   // sampled trg features
__device__ float g_part[1024];          // per-block weighted loss partials
__device__ float g_cnt [1024];          // per-block visibility counts
__device__ int   g_ctr = 0;             // last-block counter (self-resetting)

// MUFU intrinsics -------------------------------------------------------------
__device__ __forceinline__ float ex2a(float x)  { float y; asm("ex2.approx.f32 %0, %1;"  : "=f"(y) : "f"(x)); return y; }
__device__ __forceinline__ float lg2a(float x)  { float y; asm("lg2.approx.f32 %0, %1;"  : "=f"(y) : "f"(x)); return y; }
__device__ __forceinline__ float sqta(float x)  { float y; asm("sqrt.approx.f32 %0, %1;" : "=f"(y) : "f"(x)); return y; }

// Kernel 1: corner-parallel bilinear sampling ---------------------------------
// 4 threads per sample point (one per bilinear corner); 2*N*K samples total.
// grid = 2*N*K*4 / 256 = 1024 blocks. Each thread: ONE 8-byte gather.
__global__ __launch_bounds__(256) void sample_kernel(
        const float* __restrict__ sflow, const float* __restrict__ tflow,
        const float* __restrict__ skp,  const float* __restrict__ tkp) {
    int g      = blockIdx.x * blockDim.x + threadIdx.x;    // [0, 262144)
    int samp   = g >> 2;                                   // [0, 2*N*K)
    int corner = g & 3;                                    // dx = c&1, dy = c>>1
    int k      = samp & (NB * KP - 1);                     // n*K + kp
    int n      = k >> 10;
    bool is_src = samp < NB * KP;

    const float* kp   = is_src ? skp   : tkp;
    const float* flow = is_src ? sflow : tflow;
    float2 p = ((const float2*)kp)[k];

    float x0f = floorf(p.x), y0f = floorf(p.y);
    float wx  = p.x - x0f,   wy  = p.y - y0f;
    int dx = corner & 1, dy = corner >> 1;
    int xi = (int)x0f + dx, yi = (int)y0f + dy;
    float w = (dx ? wx : 1.f - wx) * (dy ? wy : 1.f - wy);

    float ax = 0.f, ay = 0.f;
    if (xi >= 0 && xi < RESO && yi >= 0 && yi < RESO) {
        const float2 v = *(const float2*)(flow + ((((size_t)n * RESO + yi) * RESO + xi) << 1));
        ax = v.x * w;
        ay = v.y * w;
    }
    // combine 4 corners within the aligned 4-lane group
    ax += __shfl_xor_sync(0xffffffffu, ax, 1);
    ay += __shfl_xor_sync(0xffffffffu, ay, 1);
    ax += __shfl_xor_sync(0xffffffffu, ax, 2);
    ay += __shfl_xor_sync(0xffffffffu, ay, 2);

    if (corner == 0) {
        if (is_src) {
            g_srcp[2 * k]     = ax + EPSF;                 // fold +eps into src side
            g_srcp[2 * k + 1] = ay + EPSF;
        } else {
            g_trgc[2 * k]     = ax;
            g_trgc[2 * k + 1] = ay;
        }
    }
}

// Kernel 2: pairwise + CE diag + per-block partial + last-block final reduce --
// 1 warp = 4 consecutive j's. Block = 8 warps = 32 j's. Grid = 32*32 = 1024.
__global__ __launch_bounds__(256) void pair_kernel(const int* __restrict__ vis,
                                                   const float* __restrict__ wt,
                                                   float* __restrict__ out) {
    __shared__ float2 sh[KP];                              // src features of batch n (8 KB)
    __shared__ float  sh_l[8], sh_v[8];
    __shared__ bool   s_last;
    const int warp = threadIdx.x >> 5, lane = threadIdx.x & 31;
    const int n     = blockIdx.x >> 5;                     // 32 blocks per batch
    const int jbase = ((blockIdx.x & 31) << 5) + (warp << 2);

    const float2* __restrict__ srcp = (const float2*)g_srcp + n * KP;
    for (int i = threadIdx.x; i < KP; i += 256) sh[i] = srcp[i];
    __syncthreads();

    const float2* __restrict__ trgn = (const float2*)g_trgc + n * KP;
    const float2 t0 = trgn[jbase + 0];
    const float2 t1 = trgn[jbase + 1];
    const float2 t2 = trgn[jbase + 2];
    const float2 t3 = trgn[jbase + 3];

    const float C1 = -1.4426950408889634f;                 // -log2(e) / T
    float a0 = 0.f, a1 = 0.f, a2 = 0.f, a3 = 0.f;
#pragma unroll 4
    for (int i = lane; i < KP; i += 32) {
        float2 s = sh[i];
        { float dx = s.x - t0.x, dy = s.y - t0.y; a0 += ex2a(sqta(fmaf(dx, dx, dy * dy)) * C1); }
        { float dx = s.x - t1.x, dy = s.y - t1.y; a1 += ex2a(sqta(fmaf(dx, dx, dy * dy)) * C1); }
        { float dx = s.x - t2.x, dy = s.y - t2.y; a2 += ex2a(sqta(fmaf(dx, dx, dy * dy)) * C1); }
        { float dx = s.x - t3.x, dy = s.y - t3.y; a3 += ex2a(sqta(fmaf(dx, dx, dy * dy)) * C1); }
    }
#pragma unroll
    for (int o = 16; o; o >>= 1) {
        a0 += __shfl_xor_sync(0xffffffffu, a0, o);
        a1 += __shfl_xor_sync(0xffffffffu, a1, o);
        a2 += __shfl_xor_sync(0xffffffffu, a2, o);
        a3 += __shfl_xor_sync(0xffffffffu, a3, o);
    }

    if (lane == 0) {
        const float LN2 = 0.6931471805599453f;
        float lsum = 0.f, vsum = 0.f;
        float acc[4] = {a0, a1, a2, a3};
        float tx[4] = {t0.x, t1.x, t2.x, t3.x};
        float ty[4] = {t0.y, t1.y, t2.y, t3.y};
#pragma unroll
        for (int q = 0; q < 4; q++) {
            int j = jbase + q;
            float2 sj = sh[j];
            float dx = sj.x - tx[q], dy = sj.y - ty[q];
            float diag = sqta(fmaf(dx, dx, dy * dy));
            // ce = ln(sum exp) + dist_jj ; d1==d2 forward => factor 2
            float loss = 2.f * fmaf(lg2a(acc[q]), LN2, diag);
            float vi = vis[n * KP + j] ? 1.f : 0.f;
            lsum = fmaf(loss * wt[n * KP + j], vi, lsum);
            vsum += vi;
        }
        sh_l[warp] = lsum; sh_v[warp] = vsum;
    }
    __syncthreads();

    if (threadIdx.x == 0) {
        float l = 0.f, v = 0.f;
#pragma unroll
        for (int w = 0; w < 8; w++) { l += sh_l[w]; v += sh_v[w]; }
        g_part[blockIdx.x] = l;
        g_cnt [blockIdx.x] = v;
        __threadfence();
        int prev = atomicAdd(&g_ctr, 1);
        s_last = (prev == 1023);
    }
    __syncthreads();

    // Last block to finish performs the final deterministic fixed-tree reduce.
    if (s_last) {
        __shared__ float fl[32], fv[32];
        // fixed order: thread t accumulates partials t, t+256, t+512, t+768
        float l = 0.f, v = 0.f;
#pragma unroll
        for (int r = 0; r < 4; r++) {
            int i = threadIdx.x + (r << 8);
            l += g_part[i];
            v += g_cnt [i];
        }
#pragma unroll
        for (int o = 16; o; o >>= 1) {
            l += __shfl_xor_sync(0xffffffffu, l, o);
            v += __shfl_xor_sync(0xffffffffu, v, o);
        }
        if (lane == 0) { fl[warp] = l; fv[warp] = v; }
        __syncthreads();
        if (threadIdx.x == 0) {
            l = 0.f; v = 0.f;
#pragma unroll
            for (int w = 0; w < 8; w++) { l += fl[w]; v += fv[w]; }
            out[0] = l / v;
            g_ctr = 0;                                     // reset for next graph replay
        }
    }
}

extern "C" void kernel_launch(void* const* d_in, const int* in_sizes, int n_in,
                              void* d_out, int out_size) {
    const float* sflow = (const float*)d_in[0];
    const float* tflow = (const float*)d_in[1];
    const float* skp   = (const float*)d_in[2];
    const float* tkp   = (const float*)d_in[3];
    const int*   vis   = (const int*)d_in[4];   // bool serialized as int32
    const float* wt    = (const float*)d_in[5];
    float*       out   = (float*)d_out;

    sample_kernel<<<(2 * NB * KP * 4) / 256, 256>>>(sflow, tflow, skp, tkp);
    pair_kernel<<<1024, 256>>>(vis, wt, out);
}

// round 9
// speedup vs baseline: 1.3372x; 1.0013x over previous
#include <cuda_runtime.h>

// Problem constants (from reference): N=32, RES=256, C=2, K=1024, T=1, EPS=1e-6
#define NB   32
#define RESO 256
#define KP   1024
#define EPSF 1e-6f
#define C1F  1.4426950408889634f          // log2(e)/T
#define UF   (C1F * C1F)                  // folded scale on squared distances
#define LN2F 0.6931471805599453f

// Scratch (no allocations allowed) --------------------------------------------
__device__ float g_sx[NB * KP];         // src.x + eps
__device__ float g_sy[NB * KP];         // src.y + eps
__device__ float g_sp[NB * KP];         // u * |src|^2
__device__ float g_tx[NB * KP];         // trg.x
__device__ float g_ty[NB * KP];         // trg.y
__device__ float g_part[1024];          // per-block weighted loss partials
__device__ float g_cnt [1024];          // per-block visibility counts
__device__ int   g_ctr = 0;             // last-block counter (self-resetting)

// MUFU intrinsics (abs/neg folded into MUFU source modifiers by ptxas) --------
__device__ __forceinline__ float lg2a(float x) { float y; asm("lg2.approx.f32 %0, %1;" : "=f"(y) : "f"(x)); return y; }
__device__ __forceinline__ float sqrt_abs(float x) {
    float y; asm("{ .reg .f32 t; abs.f32 t, %1; sqrt.approx.f32 %0, t; }" : "=f"(y) : "f"(x)); return y;
}
__device__ __forceinline__ float ex2_neg(float x) {
    float y; asm("{ .reg .f32 t; neg.f32 t, %1; ex2.approx.f32 %0, t; }" : "=f"(y) : "f"(x)); return y;
}

// Packed f32x2 helpers --------------------------------------------------------
typedef unsigned long long u64;
__device__ __forceinline__ u64 pack2(float v) {
    u64 r; asm("mov.b64 %0, {%1, %1};" : "=l"(r) : "f"(v)); return r;
}
__device__ __forceinline__ u64 add2(u64 a, u64 b) {
    u64 r; asm("add.rn.f32x2 %0, %1, %2;" : "=l"(r) : "l"(a), "l"(b)); return r;
}
__device__ __forceinline__ u64 fma2(u64 a, u64 b, u64 c) {
    u64 r; asm("fma.rn.f32x2 %0, %1, %2, %3;" : "=l"(r) : "l"(a), "l"(b), "l"(c)); return r;
}
__device__ __forceinline__ void unpack2(u64 p, float& lo, float& hi) {
    asm("mov.b64 {%0, %1}, %2;" : "=f"(lo), "=f"(hi) : "l"(p));
}

// Kernel 1: corner-parallel bilinear sampling (SoA outputs) -------------------
__global__ __launch_bounds__(256) void sample_kernel(
        const float* __restrict__ sflow, const float* __restrict__ tflow,
        const float* __restrict__ skp,  const float* __restrict__ tkp) {
    int g      = blockIdx.x * blockDim.x + threadIdx.x;    // [0, 262144)
    int samp   = g >> 2;                                   // [0, 2*N*K)
    int corner = g & 3;                                    // dx = c&1, dy = c>>1
    int k      = samp & (NB * KP - 1);                     // n*K + kp
    int n      = k >> 10;
    bool is_src = samp < NB * KP;

    const float* kp   = is_src ? skp   : tkp;
    const float* flow = is_src ? sflow : tflow;
    float2 p = ((const float2*)kp)[k];

    float x0f = floorf(p.x), y0f = floorf(p.y);
    float wx  = p.x - x0f,   wy  = p.y - y0f;
    int dx = corner & 1, dy = corner >> 1;
    int xi = (int)x0f + dx, yi = (int)y0f + dy;
    float w = (dx ? wx : 1.f - wx) * (dy ? wy : 1.f - wy);

    float ax = 0.f, ay = 0.f;
    if (xi >= 0 && xi < RESO && yi >= 0 && yi < RESO) {
        const float2 v = *(const float2*)(flow + ((((size_t)n * RESO + yi) * RESO + xi) << 1));
        ax = v.x * w;
        ay = v.y * w;
    }
    ax += __shfl_xor_sync(0xffffffffu, ax, 1);
    ay += __shfl_xor_sync(0xffffffffu, ay, 1);
    ax += __shfl_xor_sync(0xffffffffu, ax, 2);
    ay += __shfl_xor_sync(0xffffffffu, ay, 2);

    if (corner == 0) {
        if (is_src) {
            float sx = ax + EPSF, sy = ay + EPSF;          // fold +eps into src side
            g_sx[k] = sx;
            g_sy[k] = sy;
            g_sp[k] = UF * fmaf(sx, sx, sy * sy);          // u*|s|^2
        } else {
            g_tx[k] = ax;
            g_ty[k] = ay;
        }
    }
}

// Kernel 2: pairwise + CE diag + per-block partial + last-block final reduce --
// 1 warp = 4 consecutive j's; lanes process consecutive-i PAIRS (f32x2 packed).
// Block = 8 warps = 32 j's. Grid = 32*32 = 1024.
__global__ __launch_bounds__(256) void pair_kernel(const int* __restrict__ vis,
                                                   const float* __restrict__ wt,
                                                   float* __restrict__ out) {
    __shared__ float shx[KP], shy[KP], shp[KP];            // src SoA for batch n (12 KB)
    __shared__ float sh_l[8], sh_v[8];
    __shared__ bool  s_last;
    const int warp = threadIdx.x >> 5, lane = threadIdx.x & 31;
    const int n     = blockIdx.x >> 5;                     // 32 blocks per batch
    const int jbase = ((blockIdx.x & 31) << 5) + (warp << 2);

    {   // vectorized smem fill: 256 float4 per array
        const float4* gx = (const float4*)(g_sx + n * KP);
        const float4* gy = (const float4*)(g_sy + n * KP);
        const float4* gp = (const float4*)(g_sp + n * KP);
        ((float4*)shx)[threadIdx.x] = gx[threadIdx.x];
        ((float4*)shy)[threadIdx.x] = gy[threadIdx.x];
        ((float4*)shp)[threadIdx.x] = gp[threadIdx.x];
    }
    __syncthreads();

    // per-j constants (uniform across warp)
    float tx[4], ty[4], qx[4], qy[4], rr[4];
    u64 qx2[4], qy2[4], rr2[4];
#pragma unroll
    for (int q = 0; q < 4; q++) {
        tx[q] = g_tx[n * KP + jbase + q];
        ty[q] = g_ty[n * KP + jbase + q];
        qx[q] = -2.f * UF * tx[q];
        qy[q] = -2.f * UF * ty[q];
        rr[q] = UF * fmaf(tx[q], tx[q], ty[q] * ty[q]);
        qx2[q] = pack2(qx[q]);
        qy2[q] = pack2(qy[q]);
        rr2[q] = pack2(rr[q]);
    }

    float a0 = 0.f, a1 = 0.f, a2 = 0.f, a3 = 0.f;
    const u64* px = (const u64*)shx;                       // consecutive-i pairs, pre-packed
    const u64* py = (const u64*)shy;
    const u64* pp = (const u64*)shp;
#pragma unroll 4
    for (int it = 0; it < KP / 2; it += 32) {
        int pi = it + lane;
        u64 x2 = px[pi], y2 = py[pi], p2 = pp[pi];
        {   u64 d = fma2(x2, qx2[0], fma2(y2, qy2[0], add2(p2, rr2[0])));
            float lo, hi; unpack2(d, lo, hi);
            a0 += ex2_neg(sqrt_abs(lo));
            a0 += ex2_neg(sqrt_abs(hi)); }
        {   u64 d = fma2(x2, qx2[1], fma2(y2, qy2[1], add2(p2, rr2[1])));
            float lo, hi; unpack2(d, lo, hi);
            a1 += ex2_neg(sqrt_abs(lo));
            a1 += ex2_neg(sqrt_abs(hi)); }
        {   u64 d = fma2(x2, qx2[2], fma2(y2, qy2[2], add2(p2, rr2[2])));
            float lo, hi; unpack2(d, lo, hi);
            a2 += ex2_neg(sqrt_abs(lo));
            a2 += ex2_neg(sqrt_abs(hi)); }
        {   u64 d = fma2(x2, qx2[3], fma2(y2, qy2[3], add2(p2, rr2[3])));
            float lo, hi; unpack2(d, lo, hi);
            a3 += ex2_neg(sqrt_abs(lo));
            a3 += ex2_neg(sqrt_abs(hi)); }
    }
#pragma unroll
    for (int o = 16; o; o >>= 1) {
        a0 += __shfl_xor_sync(0xffffffffu, a0, o);
        a1 += __shfl_xor_sync(0xffffffffu, a1, o);
        a2 += __shfl_xor_sync(0xffffffffu, a2, o);
        a3 += __shfl_xor_sync(0xffffffffu, a3, o);
    }

    if (lane == 0) {
        float acc[4] = {a0, a1, a2, a3};
        float lsum = 0.f, vsum = 0.f;
#pragma unroll
        for (int q = 0; q < 4; q++) {
            int j = jbase + q;
            // scaled diagonal: v_jj = C1 * dist_jj (same dot form)
            float dsq = fmaf(shx[j], qx[q], fmaf(shy[j], qy[q], shp[j] + rr[q]));
            float vjj = sqrt_abs(dsq);
            // loss = 2*(ln(acc) + dist_jj) = 2*ln2*(lg2(acc) + v_jj)
            float loss = (2.f * LN2F) * (lg2a(acc[q]) + vjj);
            float vi = vis[n * KP + j] ? 1.f : 0.f;
            lsum = fmaf(loss * wt[n * KP + j], vi, lsum);
            vsum += vi;
        }
        sh_l[warp] = lsum; sh_v[warp] = vsum;
    }
    __syncthreads();

    if (threadIdx.x == 0) {
        float l = 0.f, v = 0.f;
#pragma unroll
        for (int w = 0; w < 8; w++) { l += sh_l[w]; v += sh_v[w]; }
        g_part[blockIdx.x] = l;
        g_cnt [blockIdx.x] = v;
        __threadfence();
        int prev = atomicAdd(&g_ctr, 1);
        s_last = (prev == 1023);
    }
    __syncthreads();

    // Last block performs the final deterministic fixed-tree reduce.
    if (s_last) {
        __shared__ float fl[8], fv[8];
        float l = 0.f, v = 0.f;
#pragma unroll
        for (int r = 0; r < 4; r++) {
            int i = threadIdx.x + (r << 8);
            l += g_part[i];
            v += g_cnt [i];
        }
#pragma unroll
        for (int o = 16; o; o >>= 1) {
            l += __shfl_xor_sync(0xffffffffu, l, o);
            v += __shfl_xor_sync(0xffffffffu, v, o);
        }
        if (lane == 0) { fl[warp] = l; fv[warp] = v; }
        __syncthreads();
        if (threadIdx.x == 0) {
            l = 0.f; v = 0.f;
#pragma unroll
            for (int w = 0; w < 8; w++) { l += fl[w]; v += fv[w]; }
            out[0] = l / v;
            g_ctr = 0;                                     // reset for next graph replay
        }
    }
}

extern "C" void kernel_launch(void* const* d_in, const int* in_sizes, int n_in,
                              void* d_out, int out_size) {
    const float* sflow = (const float*)d_in[0];
    const float* tflow = (const float*)d_in[1];
    const float* skp   = (const float*)d_in[2];
    const float* tkp   = (const float*)d_in[3];
    const int*   vis   = (const int*)d_in[4];   // bool serialized as int32
    const float* wt    = (const float*)d_in[5];
    float*       out   = (float*)d_out;

    sample_kernel<<<(2 * NB * KP * 4) / 256, 256>>>(sflow, tflow, skp, tkp);
    pair_kernel<<<1024, 256>>>(vis, wt, out);
}